// round 13
// baseline (speedup 1.0000x reference)
#include <cuda_runtime.h>
#include <math_constants.h>

// Problem constants: B=512, T=512, D=128, H=128
#define BB 512
#define TT 512
#define DD 128
#define HH 128

// ---------------- scratch (static __device__, zero-initialized) ----------------
__device__ float    g_r  [BB * DD];      // r vector per batch        (256 KB)
__device__ float    g_vp [BB * 4 * DD];  // partial v per (b,quarter) (1 MB)
__device__ float    g_lp [BB * 4];       // partial weight-sum per (b,quarter)
__device__ float    g_wa [BB * TT];      // fallback w buffer if out_a == null
__device__ unsigned g_cnt[BB];           // per-batch arrival counter (self-resetting)
__device__ unsigned g_rdy[BB];           // per-batch r-ready flag    (self-resetting)

// ---------------- cp.async helpers ----------------
__device__ __forceinline__ void cp_async16(void* smem_dst, const void* gmem_src) {
    unsigned s = (unsigned)__cvta_generic_to_shared(smem_dst);
    asm volatile("cp.async.cg.shared.global [%0], [%1], 16;\n" :: "r"(s), "l"(gmem_src));
}
__device__ __forceinline__ void cp_commit() {
    asm volatile("cp.async.commit_group;\n");
}
template <int N>
__device__ __forceinline__ void cp_wait() {
    asm volatile("cp.async.wait_group %0;\n" :: "n"(N));
}

// ================== single fused kernel (grid BB*4 x 128) ==================
// CTA = (b, quarter). qt==0 additionally computes r[b] and publishes it;
// quarters 1-3 spin (tid 0, acquire) until ready. Streaming loop: 4 warps x
// 32 rows, 4-row iterations, per-warp cp.async ring (3 stages x 4 rows,
// lead-2), no block barriers. Last quarter-CTA of a batch finalizes and
// resets the batch's counters (graph-replay safe).
#define KA_STAGES 3
#define KA_STAGE_F4 128                 // 4 rows * 32 float4 = 2 KB

__global__ __launch_bounds__(128, 8)
void ka_fused(const float* __restrict__ input,
              const int*   __restrict__ mask,
              const float* __restrict__ Wt,
              const float* __restrict__ Wx,
              const float* __restrict__ rate,
              float* __restrict__ wa,              // unnormalized weights [B,T]
              float* __restrict__ out_v,           // [B,D] or null
              float* __restrict__ out_a)           // [B,T] or null (== wa if present)
{
    __shared__ float4   s_ring[4][KA_STAGES * KA_STAGE_F4];   // 24 KB
    __shared__ float    s_r[DD];
    __shared__ int      s_m[128];
    __shared__ float    s_v[4][DD];
    __shared__ float    s_l[4];
    __shared__ unsigned s_last;
    // qt==0 r-computation scratch
    __shared__ float    s_lv[DD];
    __shared__ float    s_q[HH];
    __shared__ int      s_red[4];

    const int x    = blockIdx.x;
    const int b    = x >> 2;
    const int qt   = x & 3;
    const int tid  = threadIdx.x;
    const int w    = tid >> 5, lane = tid & 31;
    const int t0   = qt * 128;
    // 8-lane group -> row-in-batch: lanes 0-7:r0, 8-15:r2, 16-23:r1, 24-31:r3
    const int myrow = ((lane >> 4) & 1) + (((lane >> 3) & 1) << 1);

    const float4* __restrict__ grow =
        (const float4*)(input + ((size_t)b * TT + t0 + w * 32) * DD);
    float4* __restrict__ myring = &s_ring[w][0];

    // ---- 1. issue input prefetch FIRST (dominant HBM traffic starts now) ----
    #pragma unroll
    for (int j = 0; j < 2; j++) {
        float4* slot = myring + j * KA_STAGE_F4;
        #pragma unroll
        for (int r = 0; r < 4; r++)
            cp_async16(slot + r * 32 + lane, grow + (j * 4 + r) * 32 + lane);
        cp_commit();
    }

    // ---- 2. this quarter's mask ----
    s_m[tid] = mask[(size_t)b * TT + t0 + tid];

    // ---- 3. qt==0: compute r[b] = Wx * (Wt^T * lv[b]) and publish ----
    if (qt == 0) {
        // full-T mask sum (512 ints = 128 int4, one per thread)
        int4 mm = ((const int4*)(mask + (size_t)b * TT))[tid];
        int s = mm.x + mm.y + mm.z + mm.w;
        #pragma unroll
        for (int o = 16; o; o >>= 1) s += __shfl_xor_sync(0xffffffffu, s, o);
        if (lane == 0) s_red[w] = s;
        __syncthreads();
        int total = s_red[0] + s_red[1] + s_red[2] + s_red[3];
        int last = total - 1; if (last < 0) last = 0;

        // lv gather (coalesced 128 floats)
        s_lv[tid] = input[((size_t)b * TT + last) * DD + tid];
        __syncthreads();

        // q[h] = sum_d lv[d] * Wt[d,h]  (warp-coalesced column reads, MLP via unroll)
        {
            float acc = 0.0f;
            #pragma unroll 8
            for (int d = 0; d < DD; d++)
                acc += s_lv[d] * __ldg(&Wt[d * HH + tid]);
            s_q[tid] = acc;
        }
        __syncthreads();

        // r[d] = sum_h Wx[d,h] * q[h]  (row-contiguous float4)
        {
            const float4* wx4 = (const float4*)(Wx + (size_t)tid * HH);
            float racc = 0.0f;
            #pragma unroll
            for (int j = 0; j < HH / 4; j++) {
                float4 wv = wx4[j];
                racc += wv.x * s_q[4 * j + 0] + wv.y * s_q[4 * j + 1]
                      + wv.z * s_q[4 * j + 2] + wv.w * s_q[4 * j + 3];
            }
            g_r[(size_t)b * DD + tid] = racc;
        }
        __threadfence();
        __syncthreads();                      // all g_r writes done before flag
        if (tid == 0) atomicExch(&g_rdy[b], 1u);
    }

    // ---- 4. wait for r[b]; load it ----
    if (tid == 0 && qt != 0) {
        unsigned v;
        do {
            asm volatile("ld.acquire.gpu.global.u32 %0, [%1];"
                         : "=r"(v) : "l"(&g_rdy[b]) : "memory");
        } while (v == 0u);
    }
    __syncthreads();
    s_r[tid] = __ldcg(&g_r[(size_t)b * DD + tid]);
    __syncthreads();

    const float srate = __fdividef(1.0f, 1.0f + __expf(-rate[0]));
    const float4 rr = ((const float4*)s_r)[lane];

    float4 acc0 = make_float4(0.f, 0.f, 0.f, 0.f);
    float4 acc1 = make_float4(0.f, 0.f, 0.f, 0.f);
    float  lacc = 0.0f;

    // ---- 5. streaming main loop (R12 scheme, unchanged) ----
    #pragma unroll
    for (int i = 0; i < 8; i++) {                 // 8 iterations of 4 rows
        const int nb = i + 2;
        if (nb < 8) {
            float4* slot = myring + (nb % KA_STAGES) * KA_STAGE_F4;
            #pragma unroll
            for (int r = 0; r < 4; r++)
                cp_async16(slot + r * 32 + lane, grow + (nb * 4 + r) * 32 + lane);
        }
        cp_commit();                      // commit every iter -> wait<2> = batch i done
        cp_wait<2>();

        const float4* slot = myring + (i % KA_STAGES) * KA_STAGE_F4;
        const float4 c0 = slot[0 * 32 + lane];
        const float4 c1 = slot[1 * 32 + lane];
        const float4 c2 = slot[2 * 32 + lane];
        const float4 c3 = slot[3 * 32 + lane];

        float p0 = c0.x * rr.x + c0.y * rr.y + c0.z * rr.z + c0.w * rr.w;
        float p1 = c1.x * rr.x + c1.y * rr.y + c1.z * rr.z + c1.w * rr.w;
        float p2 = c2.x * rr.x + c2.y * rr.y + c2.z * rr.z + c2.w * rr.w;
        float p3 = c3.x * rr.x + c3.y * rr.y + c3.z * rr.z + c3.w * rr.w;

        // 9-shfl combined reduce: 8-lane group owns one row
        p0 += __shfl_xor_sync(0xffffffffu, p0, 16);
        p1 += __shfl_xor_sync(0xffffffffu, p1, 16);
        float v01 = (lane & 16) ? p1 : p0;
        p2 += __shfl_xor_sync(0xffffffffu, p2, 16);
        p3 += __shfl_xor_sync(0xffffffffu, p3, 16);
        float v23 = (lane & 16) ? p3 : p2;
        v01 += __shfl_xor_sync(0xffffffffu, v01, 8);
        v23 += __shfl_xor_sync(0xffffffffu, v23, 8);
        float v = (lane & 8) ? v23 : v01;
        v += __shfl_xor_sync(0xffffffffu, v, 4);
        v += __shfl_xor_sync(0xffffffffu, v, 2);
        v += __shfl_xor_sync(0xffffffffu, v, 1);

        // weight math once per 4 rows
        const int tl = w * 32 + 4 * i + myrow;    // local t in [0,128)
        const int tg = t0 + tl;                   // global t for decay
        float sig   = __fdividef(1.0f, 1.0f + __expf(-v));
        float denom = srate * (__logf(2.72f + (1.0f - sig)) * (float)(TT - tg));
        float e     = fmaxf(__fdividef(sig, denom), 0.0f);
        float wgt   = (s_m[tl] != 0) ? __expf(e) : 0.0f;

        if ((lane & 7) == 0) {
            wa[(size_t)b * TT + tg] = wgt;        // unnormalized
            lacc += wgt;
        }
        float w0 = __shfl_sync(0xffffffffu, wgt, 0);
        float w1 = __shfl_sync(0xffffffffu, wgt, 16);
        float w2 = __shfl_sync(0xffffffffu, wgt, 8);
        float w3 = __shfl_sync(0xffffffffu, wgt, 24);

        acc0.x += w0 * c0.x + w1 * c1.x;
        acc0.y += w0 * c0.y + w1 * c1.y;
        acc0.z += w0 * c0.z + w1 * c1.z;
        acc0.w += w0 * c0.w + w1 * c1.w;
        acc1.x += w2 * c2.x + w3 * c3.x;
        acc1.y += w2 * c2.y + w3 * c3.y;
        acc1.z += w2 * c2.z + w3 * c3.z;
        acc1.w += w2 * c2.w + w3 * c3.w;
    }

    acc0.x += acc1.x; acc0.y += acc1.y; acc0.z += acc1.z; acc0.w += acc1.w;

    // ---- 6. publish this quarter's partials ----
    ((float4*)&s_v[w][0])[lane] = acc0;
    float lw = __shfl_sync(0xffffffffu, lacc, 0) + __shfl_sync(0xffffffffu, lacc, 8)
             + __shfl_sync(0xffffffffu, lacc, 16) + __shfl_sync(0xffffffffu, lacc, 24);
    if (lane == 0) s_l[w] = lw;
    __syncthreads();

    if (tid == 0) g_lp[x] = s_l[0] + s_l[1] + s_l[2] + s_l[3];
    g_vp[(size_t)x * DD + tid] = s_v[0][tid] + s_v[1][tid] + s_v[2][tid] + s_v[3][tid];

    // ---- 7. fence + arrival; last quarter-CTA of batch b finalizes + resets ----
    __threadfence();
    if (tid == 0) s_last = atomicAdd(&g_cnt[b], 1u);
    __syncthreads();
    if (s_last == 3u) {
        float l = __ldcg(&g_lp[4 * b + 0]) + __ldcg(&g_lp[4 * b + 1])
                + __ldcg(&g_lp[4 * b + 2]) + __ldcg(&g_lp[4 * b + 3]);
        float inv = __fdividef(1.0f, l);

        if (out_v) {
            float v = __ldcg(&g_vp[(size_t)(4 * b + 0) * DD + tid])
                    + __ldcg(&g_vp[(size_t)(4 * b + 1) * DD + tid])
                    + __ldcg(&g_vp[(size_t)(4 * b + 2) * DD + tid])
                    + __ldcg(&g_vp[(size_t)(4 * b + 3) * DD + tid]);
            out_v[(size_t)b * DD + tid] = v * inv;
        }
        if (out_a) {
            #pragma unroll
            for (int j = 0; j < 4; j++) {
                size_t idx = (size_t)b * TT + j * 128 + tid;
                out_a[idx] = __ldcg(&wa[idx]) * inv;   // in-place rescale
            }
        }
        // reset batch counters for the next graph replay
        if (tid == 0) {
            g_cnt[b] = 0u;
            g_rdy[b] = 0u;
        }
    }
}

// ================== launch ==================
extern "C" void kernel_launch(void* const* d_in, const int* in_sizes, int n_in,
                              void* d_out, int out_size) {
    const float* input = (const float*)d_in[0];
    const int*   mask  = (const int*)  d_in[1];
    const float* Wt    = (const float*)d_in[2];
    const float* Wx    = (const float*)d_in[3];
    const float* rate  = (const float*)d_in[4];

    float* out = (float*)d_out;
    float* out_v = nullptr;
    float* out_a = nullptr;

    if (out_size == BB * DD + BB * TT) {        // (v, a) concatenated
        out_v = out;
        out_a = out + BB * DD;
    } else if (out_size == BB * DD) {           // v only
        out_v = out;
    } else {                                    // a only
        out_a = out;
    }

    float* wa;
    if (out_a) {
        wa = out_a;
    } else {
        cudaGetSymbolAddress((void**)&wa, g_wa);   // address query only, no alloc
    }

    ka_fused<<<BB * 4, 128>>>(input, mask, Wt, Wx, rate, wa, out_v, out_a);
}

// round 15
// speedup vs baseline: 1.3472x; 1.3472x over previous
#include <cuda_runtime.h>
#include <math_constants.h>

// Problem constants: B=512, T=512, D=128, H=128
#define BB 512
#define TT 512
#define DD 128
#define HH 128

// ---------------- scratch (static __device__, zero-initialized) ----------------
__device__ float    g_r  [BB * DD];      // r vector per batch        (256 KB)
__device__ float    g_vp [BB * 4 * DD];  // partial v per (b,quarter) (1 MB)
__device__ float    g_lp [BB * 4];       // partial weight-sum per (b,quarter)
__device__ float    g_wa [BB * TT];      // fallback w buffer if out_a == null
__device__ unsigned g_cnt[BB];           // per-batch arrival counter (self-resetting)
__device__ unsigned g_rdy[BB];           // per-batch r-ready flag    (self-resetting)

// ---------------- cp.async helpers ----------------
__device__ __forceinline__ void cp_async16(void* smem_dst, const void* gmem_src) {
    unsigned s = (unsigned)__cvta_generic_to_shared(smem_dst);
    asm volatile("cp.async.cg.shared.global [%0], [%1], 16;\n" :: "r"(s), "l"(gmem_src));
}
__device__ __forceinline__ void cp_commit() {
    asm volatile("cp.async.commit_group;\n");
}
template <int N>
__device__ __forceinline__ void cp_wait() {
    asm volatile("cp.async.wait_group %0;\n" :: "n"(N));
}

// ================== single fused kernel (grid BB*4 x 128) ==================
// CTA = (b, quarter). qt==0 computes r[b] with warp-parallel row-major GEMV
// stages and publishes it (fence + flag); quarters 1-3 spin (tid 0, acquire).
// Streaming: 4 warps x 32 rows, 4-row iterations, per-warp cp.async ring
// (3 stages x 4 rows, lead-2), no block barriers in the loop. Last quarter
// of a batch finalizes and resets that batch's counters (replay-safe).
#define KA_STAGES 3
#define KA_STAGE_F4 128                 // 4 rows * 32 float4 = 2 KB

__global__ __launch_bounds__(128, 8)
void ka_fused(const float* __restrict__ input,
              const int*   __restrict__ mask,
              const float* __restrict__ Wt,
              const float* __restrict__ Wx,
              const float* __restrict__ rate,
              float* __restrict__ wa,              // unnormalized weights [B,T]
              float* __restrict__ out_v,           // [B,D] or null
              float* __restrict__ out_a)           // [B,T] or null (== wa if present)
{
    __shared__ float4   s_ring[4][KA_STAGES * KA_STAGE_F4];   // 24 KB
    __shared__ __align__(16) float s_r[DD];
    __shared__ __align__(16) int   s_m[128];
    __shared__ __align__(16) float s_v[4][DD];
    __shared__ float    s_l[4];
    __shared__ unsigned s_last;
    // qt==0 r-computation scratch (ALL float4-cast arrays 16B-aligned)
    __shared__ __align__(16) float s_lv[DD];
    __shared__ __align__(16) float s_qp[4][HH];    // per-warp q partials
    __shared__ __align__(16) float s_q[HH];
    __shared__ int      s_red[4];

    const int x    = blockIdx.x;
    const int b    = x >> 2;
    const int qt   = x & 3;
    const int tid  = threadIdx.x;
    const int w    = tid >> 5, lane = tid & 31;
    const int t0   = qt * 128;
    // 8-lane group -> row-in-batch: lanes 0-7:r0, 8-15:r2, 16-23:r1, 24-31:r3
    const int myrow = ((lane >> 4) & 1) + (((lane >> 3) & 1) << 1);

    const float4* __restrict__ grow =
        (const float4*)(input + ((size_t)b * TT + t0 + w * 32) * DD);
    float4* __restrict__ myring = &s_ring[w][0];

    // ---- 1. issue input prefetch FIRST (dominant HBM traffic starts now) ----
    #pragma unroll
    for (int j = 0; j < 2; j++) {
        float4* slot = myring + j * KA_STAGE_F4;
        #pragma unroll
        for (int r = 0; r < 4; r++)
            cp_async16(slot + r * 32 + lane, grow + (j * 4 + r) * 32 + lane);
        cp_commit();
    }

    // ---- 2. this quarter's mask ----
    s_m[tid] = mask[(size_t)b * TT + t0 + tid];

    // ---- 3. qt==0: compute r[b] = Wx * (Wt^T * lv[b]), publish ----
    if (qt == 0) {
        // full-T mask sum (512 ints = 128 int4, one per thread)
        int4 mm = ((const int4*)(mask + (size_t)b * TT))[tid];
        int s = mm.x + mm.y + mm.z + mm.w;
        #pragma unroll
        for (int o = 16; o; o >>= 1) s += __shfl_xor_sync(0xffffffffu, s, o);
        if (lane == 0) s_red[w] = s;
        __syncthreads();
        int total = s_red[0] + s_red[1] + s_red[2] + s_red[3];
        int last = total - 1; if (last < 0) last = 0;

        // lv gather (coalesced 128 floats)
        s_lv[tid] = input[((size_t)b * TT + last) * DD + tid];
        __syncthreads();

        // q-stage: warp w owns d in [32w, 32w+32). Lane l accumulates float4
        // over h = 4l..4l+3 with coalesced row-major Wt loads (MLP-deep).
        {
            const float4* wt4 = (const float4*)Wt;
            float4 qp = make_float4(0.f, 0.f, 0.f, 0.f);
            #pragma unroll 8
            for (int j = 0; j < 32; j++) {
                const int d = 32 * w + j;
                const float lv = s_lv[d];
                const float4 wt = wt4[d * 32 + lane];
                qp.x += lv * wt.x; qp.y += lv * wt.y;
                qp.z += lv * wt.z; qp.w += lv * wt.w;
            }
            ((float4*)&s_qp[w][0])[lane] = qp;
        }
        __syncthreads();
        s_q[tid] = s_qp[0][tid] + s_qp[1][tid] + s_qp[2][tid] + s_qp[3][tid];
        __syncthreads();

        // r-stage: warp w owns 32 Wx rows; per row coalesced float4 load,
        // 4-FMA partial, 5-shfl butterfly; lane j keeps row 32w+j.
        {
            const float4* wx4 = (const float4*)Wx;
            const float4 q4 = ((const float4*)s_q)[lane];
            float rkeep = 0.0f;
            #pragma unroll 4
            for (int j = 0; j < 32; j++) {
                const int d = 32 * w + j;
                float4 wv = wx4[d * 32 + lane];
                float p = wv.x * q4.x + wv.y * q4.y + wv.z * q4.z + wv.w * q4.w;
                #pragma unroll
                for (int o = 16; o; o >>= 1) p += __shfl_xor_sync(0xffffffffu, p, o);
                if (lane == j) rkeep = p;
            }
            g_r[(size_t)b * DD + 32 * w + lane] = rkeep;   // coalesced
        }
        __threadfence();
        __syncthreads();                      // all g_r writes done before flag
        if (tid == 0) atomicExch(&g_rdy[b], 1u);
    }

    // ---- 4. wait for r[b]; load it ----
    if (tid == 0 && qt != 0) {
        unsigned v;
        do {
            asm volatile("ld.acquire.gpu.global.u32 %0, [%1];"
                         : "=r"(v) : "l"(&g_rdy[b]) : "memory");
        } while (v == 0u);
    }
    __syncthreads();
    s_r[tid] = __ldcg(&g_r[(size_t)b * DD + tid]);
    __syncthreads();

    const float srate = __fdividef(1.0f, 1.0f + __expf(-rate[0]));
    const float4 rr = ((const float4*)s_r)[lane];

    float4 acc0 = make_float4(0.f, 0.f, 0.f, 0.f);
    float4 acc1 = make_float4(0.f, 0.f, 0.f, 0.f);
    float  lacc = 0.0f;

    // ---- 5. streaming main loop (R12 scheme, unchanged) ----
    #pragma unroll
    for (int i = 0; i < 8; i++) {                 // 8 iterations of 4 rows
        const int nb = i + 2;
        if (nb < 8) {
            float4* slot = myring + (nb % KA_STAGES) * KA_STAGE_F4;
            #pragma unroll
            for (int r = 0; r < 4; r++)
                cp_async16(slot + r * 32 + lane, grow + (nb * 4 + r) * 32 + lane);
        }
        cp_commit();                      // commit every iter -> wait<2> = batch i done
        cp_wait<2>();

        const float4* slot = myring + (i % KA_STAGES) * KA_STAGE_F4;
        const float4 c0 = slot[0 * 32 + lane];
        const float4 c1 = slot[1 * 32 + lane];
        const float4 c2 = slot[2 * 32 + lane];
        const float4 c3 = slot[3 * 32 + lane];

        float p0 = c0.x * rr.x + c0.y * rr.y + c0.z * rr.z + c0.w * rr.w;
        float p1 = c1.x * rr.x + c1.y * rr.y + c1.z * rr.z + c1.w * rr.w;
        float p2 = c2.x * rr.x + c2.y * rr.y + c2.z * rr.z + c2.w * rr.w;
        float p3 = c3.x * rr.x + c3.y * rr.y + c3.z * rr.z + c3.w * rr.w;

        // 9-shfl combined reduce: 8-lane group owns one row
        p0 += __shfl_xor_sync(0xffffffffu, p0, 16);
        p1 += __shfl_xor_sync(0xffffffffu, p1, 16);
        float v01 = (lane & 16) ? p1 : p0;
        p2 += __shfl_xor_sync(0xffffffffu, p2, 16);
        p3 += __shfl_xor_sync(0xffffffffu, p3, 16);
        float v23 = (lane & 16) ? p3 : p2;
        v01 += __shfl_xor_sync(0xffffffffu, v01, 8);
        v23 += __shfl_xor_sync(0xffffffffu, v23, 8);
        float v = (lane & 8) ? v23 : v01;
        v += __shfl_xor_sync(0xffffffffu, v, 4);
        v += __shfl_xor_sync(0xffffffffu, v, 2);
        v += __shfl_xor_sync(0xffffffffu, v, 1);

        // weight math once per 4 rows
        const int tl = w * 32 + 4 * i + myrow;    // local t in [0,128)
        const int tg = t0 + tl;                   // global t for decay
        float sig   = __fdividef(1.0f, 1.0f + __expf(-v));
        float denom = srate * (__logf(2.72f + (1.0f - sig)) * (float)(TT - tg));
        float e     = fmaxf(__fdividef(sig, denom), 0.0f);
        float wgt   = (s_m[tl] != 0) ? __expf(e) : 0.0f;

        if ((lane & 7) == 0) {
            wa[(size_t)b * TT + tg] = wgt;        // unnormalized
            lacc += wgt;
        }
        float w0 = __shfl_sync(0xffffffffu, wgt, 0);
        float w1 = __shfl_sync(0xffffffffu, wgt, 16);
        float w2 = __shfl_sync(0xffffffffu, wgt, 8);
        float w3 = __shfl_sync(0xffffffffu, wgt, 24);

        acc0.x += w0 * c0.x + w1 * c1.x;
        acc0.y += w0 * c0.y + w1 * c1.y;
        acc0.z += w0 * c0.z + w1 * c1.z;
        acc0.w += w0 * c0.w + w1 * c1.w;
        acc1.x += w2 * c2.x + w3 * c3.x;
        acc1.y += w2 * c2.y + w3 * c3.y;
        acc1.z += w2 * c2.z + w3 * c3.z;
        acc1.w += w2 * c2.w + w3 * c3.w;
    }

    acc0.x += acc1.x; acc0.y += acc1.y; acc0.z += acc1.z; acc0.w += acc1.w;

    // ---- 6. publish this quarter's partials ----
    ((float4*)&s_v[w][0])[lane] = acc0;
    float lw = __shfl_sync(0xffffffffu, lacc, 0) + __shfl_sync(0xffffffffu, lacc, 8)
             + __shfl_sync(0xffffffffu, lacc, 16) + __shfl_sync(0xffffffffu, lacc, 24);
    if (lane == 0) s_l[w] = lw;
    __syncthreads();

    if (tid == 0) g_lp[x] = s_l[0] + s_l[1] + s_l[2] + s_l[3];
    g_vp[(size_t)x * DD + tid] = s_v[0][tid] + s_v[1][tid] + s_v[2][tid] + s_v[3][tid];

    // ---- 7. fence + arrival; last quarter-CTA of batch b finalizes + resets ----
    __threadfence();
    if (tid == 0) s_last = atomicAdd(&g_cnt[b], 1u);
    __syncthreads();
    if (s_last == 3u) {
        float l = __ldcg(&g_lp[4 * b + 0]) + __ldcg(&g_lp[4 * b + 1])
                + __ldcg(&g_lp[4 * b + 2]) + __ldcg(&g_lp[4 * b + 3]);
        float inv = __fdividef(1.0f, l);

        if (out_v) {
            float v = __ldcg(&g_vp[(size_t)(4 * b + 0) * DD + tid])
                    + __ldcg(&g_vp[(size_t)(4 * b + 1) * DD + tid])
                    + __ldcg(&g_vp[(size_t)(4 * b + 2) * DD + tid])
                    + __ldcg(&g_vp[(size_t)(4 * b + 3) * DD + tid]);
            out_v[(size_t)b * DD + tid] = v * inv;
        }
        if (out_a) {
            #pragma unroll
            for (int j = 0; j < 4; j++) {
                size_t idx = (size_t)b * TT + j * 128 + tid;
                out_a[idx] = __ldcg(&wa[idx]) * inv;   // in-place rescale
            }
        }
        // reset batch counters for the next graph replay
        if (tid == 0) {
            g_cnt[b] = 0u;
            g_rdy[b] = 0u;
        }
    }
}

// ================== launch ==================
extern "C" void kernel_launch(void* const* d_in, const int* in_sizes, int n_in,
                              void* d_out, int out_size) {
    const float* input = (const float*)d_in[0];
    const int*   mask  = (const int*)  d_in[1];
    const float* Wt    = (const float*)d_in[2];
    const float* Wx    = (const float*)d_in[3];
    const float* rate  = (const float*)d_in[4];

    float* out = (float*)d_out;
    float* out_v = nullptr;
    float* out_a = nullptr;

    if (out_size == BB * DD + BB * TT) {        // (v, a) concatenated
        out_v = out;
        out_a = out + BB * DD;
    } else if (out_size == BB * DD) {           // v only
        out_v = out;
    } else {                                    // a only
        out_a = out;
    }

    float* wa;
    if (out_a) {
        wa = out_a;
    } else {
        cudaGetSymbolAddress((void**)&wa, g_wa);   // address query only, no alloc
    }

    ka_fused<<<BB * 4, 128>>>(input, mask, Wt, Wx, rate, wa, out_v, out_a);
}

// round 16
// speedup vs baseline: 1.4186x; 1.0530x over previous
#include <cuda_runtime.h>
#include <math_constants.h>

// Problem constants: B=512, T=512, D=128, H=128
#define BB 512
#define TT 512
#define DD 128
#define HH 128

// ---------------- scratch (static __device__ allowed) ----------------
__device__ float    g_r [BB * DD];       // r vector per batch        (256 KB)
__device__ float    g_vp[BB * 4 * DD];   // partial v per (b,quarter) (1 MB)
__device__ float    g_lp[BB * 4];        // partial weight-sum per (b,quarter)
__device__ float    g_wa[BB * TT];       // fallback w buffer if out_a == null
__device__ unsigned g_cnt[BB];           // per-batch arrival counter (zeroed by k0)

// ---------------- cp.async helpers ----------------
__device__ __forceinline__ void cp_async16(void* smem_dst, const void* gmem_src) {
    unsigned s = (unsigned)__cvta_generic_to_shared(smem_dst);
    asm volatile("cp.async.cg.shared.global [%0], [%1], 16;\n" :: "r"(s), "l"(gmem_src));
}
__device__ __forceinline__ void cp_commit() {
    asm volatile("cp.async.commit_group;\n");
}
template <int N>
__device__ __forceinline__ void cp_wait() {
    asm volatile("cp.async.wait_group %0;\n" :: "n"(N));
}

// ================== K0: prologue, 1 batch/CTA (grid BB x 128) ==================
// Warp-parallel GEMV stages (validated in R15): q-stage = row-major coalesced
// Wt float4 reads; r-stage = warp-owned Wx rows + 5-shfl butterfly. 512
// independent chains overlap across SMs. Also zeroes g_cnt[b].
__global__ __launch_bounds__(128)
void k0_prologue(const float* __restrict__ input,   // [B,T,D]
                 const int*   __restrict__ mask,    // [B,T]
                 const float* __restrict__ Wt,      // [D,H]
                 const float* __restrict__ Wx)      // [D,H]
{
    __shared__ __align__(16) float s_lv[DD];
    __shared__ __align__(16) float s_qp[4][HH];   // per-warp q partials
    __shared__ __align__(16) float s_q[HH];
    __shared__ int s_red[4];

    const int b    = blockIdx.x;
    const int tid  = threadIdx.x;
    const int w    = tid >> 5, lane = tid & 31;

    if (tid == 0) g_cnt[b] = 0u;         // reset arrival counter for ka_fused

    // ---- mask sum: 512 ints = 128 int4, one per thread ----
    int4 mm = ((const int4*)(mask + (size_t)b * TT))[tid];
    int s = mm.x + mm.y + mm.z + mm.w;
    #pragma unroll
    for (int o = 16; o; o >>= 1) s += __shfl_xor_sync(0xffffffffu, s, o);
    if (lane == 0) s_red[w] = s;
    __syncthreads();
    int total = s_red[0] + s_red[1] + s_red[2] + s_red[3];
    int last = total - 1; if (last < 0) last = 0;

    // ---- lv gather (coalesced 128 floats) ----
    s_lv[tid] = input[((size_t)b * TT + last) * DD + tid];
    __syncthreads();

    // ---- q-stage: warp w owns d in [32w, 32w+32); lane l holds h=4l..4l+3 ----
    {
        const float4* wt4 = (const float4*)Wt;
        float4 qp = make_float4(0.f, 0.f, 0.f, 0.f);
        #pragma unroll 8
        for (int j = 0; j < 32; j++) {
            const int d = 32 * w + j;
            const float lv = s_lv[d];
            const float4 wt = wt4[d * 32 + lane];      // coalesced 128B rows
            qp.x += lv * wt.x; qp.y += lv * wt.y;
            qp.z += lv * wt.z; qp.w += lv * wt.w;
        }
        ((float4*)&s_qp[w][0])[lane] = qp;
    }
    __syncthreads();
    s_q[tid] = s_qp[0][tid] + s_qp[1][tid] + s_qp[2][tid] + s_qp[3][tid];
    __syncthreads();

    // ---- r-stage: warp w owns 32 Wx rows; lane j keeps row 32w+j ----
    {
        const float4* wx4 = (const float4*)Wx;
        const float4 q4 = ((const float4*)s_q)[lane];
        float rkeep = 0.0f;
        #pragma unroll 4
        for (int j = 0; j < 32; j++) {
            const int d = 32 * w + j;
            float4 wv = wx4[d * 32 + lane];            // coalesced
            float p = wv.x * q4.x + wv.y * q4.y + wv.z * q4.z + wv.w * q4.w;
            #pragma unroll
            for (int o = 16; o; o >>= 1) p += __shfl_xor_sync(0xffffffffu, p, o);
            if (lane == j) rkeep = p;
        }
        g_r[(size_t)b * DD + 32 * w + lane] = rkeep;   // coalesced
    }
}

// ================== KA: streaming + fused finalize (grid BB*4 x 128) ==================
// Byte-for-byte the R12 kernel (31.9us, DRAM 54%): CTA = (b, quarter), 4 warps
// x 32 rows, 4-row iterations, per-warp cp.async ring (3 stages x 4 rows,
// lead-2), no block barriers in the loop. Last quarter-CTA finalizes batch.
#define KA_STAGES 3
#define KA_STAGE_F4 128                 // 4 rows * 32 float4 = 2 KB

__global__ __launch_bounds__(128, 8)
void ka_fused(const float* __restrict__ input,
              const int*   __restrict__ mask,
              const float* __restrict__ rate,
              float* __restrict__ wa,              // unnormalized weights [B,T]
              float* __restrict__ out_v,           // [B,D] or null
              float* __restrict__ out_a)           // [B,T] or null (== wa if present)
{
    __shared__ float4   s_ring[4][KA_STAGES * KA_STAGE_F4];   // 24 KB
    __shared__ __align__(16) float s_r[DD];
    __shared__ __align__(16) int   s_m[128];
    __shared__ __align__(16) float s_v[4][DD];
    __shared__ float    s_l[4];
    __shared__ unsigned s_last;

    const int x    = blockIdx.x;
    const int b    = x >> 2;
    const int qt   = x & 3;
    const int tid  = threadIdx.x;
    const int w    = tid >> 5, lane = tid & 31;
    const int t0   = qt * 128;
    // 8-lane group -> row-in-batch: lanes 0-7:r0, 8-15:r2, 16-23:r1, 24-31:r3
    const int myrow = ((lane >> 4) & 1) + (((lane >> 3) & 1) << 1);

    const float4* __restrict__ grow =
        (const float4*)(input + ((size_t)b * TT + t0 + w * 32) * DD);
    float4* __restrict__ myring = &s_ring[w][0];

    // prefetch batches 0,1 (4 rows each)
    #pragma unroll
    for (int j = 0; j < 2; j++) {
        float4* slot = myring + j * KA_STAGE_F4;
        #pragma unroll
        for (int r = 0; r < 4; r++)
            cp_async16(slot + r * 32 + lane, grow + (j * 4 + r) * 32 + lane);
        cp_commit();
    }

    // prologue loads (overlap with prefetch)
    s_r[tid] = g_r[b * DD + tid];
    s_m[tid] = mask[(size_t)b * TT + t0 + tid];
    __syncthreads();

    const float srate = __fdividef(1.0f, 1.0f + __expf(-rate[0]));
    const float4 rr = ((const float4*)s_r)[lane];

    float4 acc0 = make_float4(0.f, 0.f, 0.f, 0.f);
    float4 acc1 = make_float4(0.f, 0.f, 0.f, 0.f);
    float  lacc = 0.0f;

    #pragma unroll
    for (int i = 0; i < 8; i++) {                 // 8 iterations of 4 rows
        const int nb = i + 2;
        if (nb < 8) {
            float4* slot = myring + (nb % KA_STAGES) * KA_STAGE_F4;
            #pragma unroll
            for (int r = 0; r < 4; r++)
                cp_async16(slot + r * 32 + lane, grow + (nb * 4 + r) * 32 + lane);
        }
        cp_commit();                      // commit every iter -> wait<2> = batch i done
        cp_wait<2>();

        const float4* slot = myring + (i % KA_STAGES) * KA_STAGE_F4;
        const float4 c0 = slot[0 * 32 + lane];
        const float4 c1 = slot[1 * 32 + lane];
        const float4 c2 = slot[2 * 32 + lane];
        const float4 c3 = slot[3 * 32 + lane];

        float p0 = c0.x * rr.x + c0.y * rr.y + c0.z * rr.z + c0.w * rr.w;
        float p1 = c1.x * rr.x + c1.y * rr.y + c1.z * rr.z + c1.w * rr.w;
        float p2 = c2.x * rr.x + c2.y * rr.y + c2.z * rr.z + c2.w * rr.w;
        float p3 = c3.x * rr.x + c3.y * rr.y + c3.z * rr.z + c3.w * rr.w;

        // 9-shfl combined reduce: 8-lane group owns one row
        p0 += __shfl_xor_sync(0xffffffffu, p0, 16);
        p1 += __shfl_xor_sync(0xffffffffu, p1, 16);
        float v01 = (lane & 16) ? p1 : p0;
        p2 += __shfl_xor_sync(0xffffffffu, p2, 16);
        p3 += __shfl_xor_sync(0xffffffffu, p3, 16);
        float v23 = (lane & 16) ? p3 : p2;
        v01 += __shfl_xor_sync(0xffffffffu, v01, 8);
        v23 += __shfl_xor_sync(0xffffffffu, v23, 8);
        float v = (lane & 8) ? v23 : v01;
        v += __shfl_xor_sync(0xffffffffu, v, 4);
        v += __shfl_xor_sync(0xffffffffu, v, 2);
        v += __shfl_xor_sync(0xffffffffu, v, 1);

        // weight math once per 4 rows
        const int tl = w * 32 + 4 * i + myrow;    // local t in [0,128)
        const int tg = t0 + tl;                   // global t for decay
        float sig   = __fdividef(1.0f, 1.0f + __expf(-v));
        float denom = srate * (__logf(2.72f + (1.0f - sig)) * (float)(TT - tg));
        float e     = fmaxf(__fdividef(sig, denom), 0.0f);
        float wgt   = (s_m[tl] != 0) ? __expf(e) : 0.0f;

        if ((lane & 7) == 0) {
            wa[(size_t)b * TT + tg] = wgt;        // unnormalized
            lacc += wgt;
        }
        float w0 = __shfl_sync(0xffffffffu, wgt, 0);
        float w1 = __shfl_sync(0xffffffffu, wgt, 16);
        float w2 = __shfl_sync(0xffffffffu, wgt, 8);
        float w3 = __shfl_sync(0xffffffffu, wgt, 24);

        acc0.x += w0 * c0.x + w1 * c1.x;
        acc0.y += w0 * c0.y + w1 * c1.y;
        acc0.z += w0 * c0.z + w1 * c1.z;
        acc0.w += w0 * c0.w + w1 * c1.w;
        acc1.x += w2 * c2.x + w3 * c3.x;
        acc1.y += w2 * c2.y + w3 * c3.y;
        acc1.z += w2 * c2.z + w3 * c3.z;
        acc1.w += w2 * c2.w + w3 * c3.w;
    }

    acc0.x += acc1.x; acc0.y += acc1.y; acc0.z += acc1.z; acc0.w += acc1.w;

    // ---- publish this quarter's partials ----
    ((float4*)&s_v[w][0])[lane] = acc0;
    float lw = __shfl_sync(0xffffffffu, lacc, 0) + __shfl_sync(0xffffffffu, lacc, 8)
             + __shfl_sync(0xffffffffu, lacc, 16) + __shfl_sync(0xffffffffu, lacc, 24);
    if (lane == 0) s_l[w] = lw;
    __syncthreads();

    if (tid == 0) g_lp[x] = s_l[0] + s_l[1] + s_l[2] + s_l[3];
    g_vp[(size_t)x * DD + tid] = s_v[0][tid] + s_v[1][tid] + s_v[2][tid] + s_v[3][tid];

    // ---- fence + arrival; last quarter-CTA of batch b finalizes ----
    __threadfence();
    if (tid == 0) s_last = atomicAdd(&g_cnt[b], 1u);
    __syncthreads();
    if (s_last == 3u) {
        float l = __ldcg(&g_lp[4 * b + 0]) + __ldcg(&g_lp[4 * b + 1])
                + __ldcg(&g_lp[4 * b + 2]) + __ldcg(&g_lp[4 * b + 3]);
        float inv = __fdividef(1.0f, l);

        if (out_v) {
            float v = __ldcg(&g_vp[(size_t)(4 * b + 0) * DD + tid])
                    + __ldcg(&g_vp[(size_t)(4 * b + 1) * DD + tid])
                    + __ldcg(&g_vp[(size_t)(4 * b + 2) * DD + tid])
                    + __ldcg(&g_vp[(size_t)(4 * b + 3) * DD + tid]);
            out_v[(size_t)b * DD + tid] = v * inv;
        }
        if (out_a) {
            #pragma unroll
            for (int j = 0; j < 4; j++) {
                size_t idx = (size_t)b * TT + j * 128 + tid;
                out_a[idx] = __ldcg(&wa[idx]) * inv;   // in-place rescale
            }
        }
    }
}

// ================== launch ==================
extern "C" void kernel_launch(void* const* d_in, const int* in_sizes, int n_in,
                              void* d_out, int out_size) {
    const float* input = (const float*)d_in[0];
    const int*   mask  = (const int*)  d_in[1];
    const float* Wt    = (const float*)d_in[2];
    const float* Wx    = (const float*)d_in[3];
    const float* rate  = (const float*)d_in[4];

    float* out = (float*)d_out;
    float* out_v = nullptr;
    float* out_a = nullptr;

    if (out_size == BB * DD + BB * TT) {        // (v, a) concatenated
        out_v = out;
        out_a = out + BB * DD;
    } else if (out_size == BB * DD) {           // v only
        out_v = out;
    } else {                                    // a only
        out_a = out;
    }

    float* wa;
    if (out_a) {
        wa = out_a;
    } else {
        cudaGetSymbolAddress((void**)&wa, g_wa);   // address query only, no alloc
    }

    k0_prologue<<<BB, 128>>>(input, mask, Wt, Wx);
    ka_fused   <<<BB * 4, 128>>>(input, mask, rate, wa, out_v, out_a);
}

// round 17
// speedup vs baseline: 1.7194x; 1.2120x over previous
#include <cuda_runtime.h>
#include <math_constants.h>

// Problem constants: B=512, T=512, D=128, H=128
#define BB 512
#define TT 512
#define DD 128
#define HH 128

// ---------------- scratch (static __device__ allowed) ----------------
__device__ float g_r[BB * DD];           // r vector per batch (256 KB)

// ---------------- cp.async helpers ----------------
__device__ __forceinline__ void cp_async16(void* smem_dst, const void* gmem_src) {
    unsigned s = (unsigned)__cvta_generic_to_shared(smem_dst);
    asm volatile("cp.async.cg.shared.global [%0], [%1], 16;\n" :: "r"(s), "l"(gmem_src));
}
__device__ __forceinline__ void cp_commit() {
    asm volatile("cp.async.commit_group;\n");
}
template <int N>
__device__ __forceinline__ void cp_wait() {
    asm volatile("cp.async.wait_group %0;\n" :: "n"(N));
}

// ================== K0: prologue, 4 batches/CTA (grid BB/4 x 256) ==================
// R12's measured-best prologue: Wt staged via cp.async (overlapped with per-warp
// mask/gather), broadcast-FMA Q stage from SMEM, R stage reads Wx rows from
// global (L1-cached).
__global__ __launch_bounds__(256)
void k0_prologue(const float* __restrict__ input,   // [B,T,D]
                 const int*   __restrict__ mask,    // [B,T]
                 const float* __restrict__ Wt,      // [D,H]
                 const float* __restrict__ Wx)      // [D,H]
{
    extern __shared__ float sWt[];       // [DD*HH] = 64 KB, layout [d][h]

    __shared__ float4 s_lvT4[DD];        // lv packed per d: (.x=b0 .. .w=b3)
    __shared__ float4 s_qp4[2][HH];      // Q partials (2 d-chunks)
    __shared__ float4 s_q4[HH];          // q packed per h
    __shared__ float4 s_rp4[2][DD];      // R partials (2 h-chunks)

    const int tid  = threadIdx.x;
    const int warp = tid >> 5, lane = tid & 31;
    const int b0   = blockIdx.x * 4;

    // ---- 1. stage Wt -> sWt via cp.async ----
    {
        const float4* src = (const float4*)Wt;
        float4* dst = (float4*)sWt;
        #pragma unroll
        for (int j = 0; j < 16; j++)
            cp_async16(dst + tid + j * 256, src + tid + j * 256);
        cp_commit();
    }

    // ---- 2. warps 0-3: mask sum + last_visit gather ----
    if (warp < 4) {
        const int bb = b0 + warp;
        const int4* m4 = (const int4*)(mask + (size_t)bb * TT);
        int s = 0;
        #pragma unroll
        for (int j = 0; j < 4; j++) {
            int4 m = m4[lane + 32 * j];
            s += m.x + m.y + m.z + m.w;
        }
        #pragma unroll
        for (int o = 16; o; o >>= 1) s += __shfl_xor_sync(0xffffffffu, s, o);
        int last = s - 1; if (last < 0) last = 0;

        const float4* lvsrc = (const float4*)(input + ((size_t)bb * TT + last) * DD);
        float4 lv = lvsrc[lane];
        float* s_lvT = (float*)s_lvT4;
        s_lvT[(4 * lane + 0) * 4 + warp] = lv.x;
        s_lvT[(4 * lane + 1) * 4 + warp] = lv.y;
        s_lvT[(4 * lane + 2) * 4 + warp] = lv.z;
        s_lvT[(4 * lane + 3) * 4 + warp] = lv.w;
    }

    cp_wait<0>();
    __syncthreads();

    // ---- 3. Q stage ----
    {
        const int c = tid >> 7, h = tid & 127;
        float4 acc = make_float4(0.f, 0.f, 0.f, 0.f);
        #pragma unroll 8
        for (int d = c * 64; d < c * 64 + 64; d++) {
            float  w  = sWt[d * HH + h];
            float4 lv = s_lvT4[d];
            acc.x += w * lv.x; acc.y += w * lv.y;
            acc.z += w * lv.z; acc.w += w * lv.w;
        }
        s_qp4[c][h] = acc;
    }
    __syncthreads();
    if (tid < HH) {
        float4 a = s_qp4[0][tid], b = s_qp4[1][tid];
        s_q4[tid] = make_float4(a.x + b.x, a.y + b.y, a.z + b.z, a.w + b.w);
    }
    __syncthreads();

    // ---- 4. R stage: Wx rows from global (L1-cached) ----
    {
        const int c = tid >> 7, d = tid & 127;
        const float4* wxrow = (const float4*)(Wx + (size_t)d * HH) + c * 16;
        float4 acc = make_float4(0.f, 0.f, 0.f, 0.f);
        #pragma unroll
        for (int j = 0; j < 16; j++) {
            float4 w = wxrow[j];
            const int h = c * 64 + j * 4;
            float4 q0 = s_q4[h + 0], q1 = s_q4[h + 1];
            float4 q2 = s_q4[h + 2], q3 = s_q4[h + 3];
            acc.x += w.x * q0.x + w.y * q1.x + w.z * q2.x + w.w * q3.x;
            acc.y += w.x * q0.y + w.y * q1.y + w.z * q2.y + w.w * q3.y;
            acc.z += w.x * q0.z + w.y * q1.z + w.z * q2.z + w.w * q3.z;
            acc.w += w.x * q0.w + w.y * q1.w + w.z * q2.w + w.w * q3.w;
        }
        s_rp4[c][d] = acc;
    }
    __syncthreads();
    if (tid < DD) {
        float4 a = s_rp4[0][tid], b = s_rp4[1][tid];
        g_r[(size_t)(b0 + 0) * DD + tid] = a.x + b.x;
        g_r[(size_t)(b0 + 1) * DD + tid] = a.y + b.y;
        g_r[(size_t)(b0 + 2) * DD + tid] = a.z + b.z;
        g_r[(size_t)(b0 + 3) * DD + tid] = a.w + b.w;
    }
}

// ================== KA: one CTA per batch, in-CTA finalize (grid BB x 256) ==================
// 8 warps x 64 rows. 4-row iterations (proven R12 body). Per-warp cp.async
// ring: 3 stages x 4 rows (48 KB dynamic), lead-2, no block barriers in the
// loop. Mask served from registers via shfl (no SMEM). Softmax finalized in
// SMEM; outputs written directly — no global partials, no atomics.
#define KA_STAGES 3
#define KA_STAGE_F4 128                 // 4 rows * 32 float4 = 2 KB

__global__ __launch_bounds__(256, 4)
void ka_single(const float* __restrict__ input,
               const int*   __restrict__ mask,
               const float* __restrict__ rate,
               float* __restrict__ out_v,           // [B,D] or null
               float* __restrict__ out_a)           // [B,T] or null
{
    extern __shared__ float4 s_ring[];               // [8][KA_STAGES*KA_STAGE_F4] = 48 KB
    __shared__ __align__(16) float s_r[DD];
    __shared__ __align__(16) float s_w[TT];          // unnormalized weights
    __shared__ __align__(16) float s_v[8][DD];       // per-warp partial v
    __shared__ float s_l[8];

    const int b    = blockIdx.x;
    const int tid  = threadIdx.x;
    const int w    = tid >> 5, lane = tid & 31;
    // 8-lane group -> row-in-batch: lanes 0-7:r0, 8-15:r2, 16-23:r1, 24-31:r3
    const int myrow = ((lane >> 4) & 1) + (((lane >> 3) & 1) << 1);

    // warp w owns rows [64w, 64w+64)
    const float4* __restrict__ grow =
        (const float4*)(input + ((size_t)b * TT + w * 64) * DD);
    float4* __restrict__ myring = s_ring + w * (KA_STAGES * KA_STAGE_F4);

    // ---- prefetch batches 0,1 (4 rows each) ----
    #pragma unroll
    for (int j = 0; j < 2; j++) {
        float4* slot = myring + j * KA_STAGE_F4;
        #pragma unroll
        for (int r = 0; r < 4; r++)
            cp_async16(slot + r * 32 + lane, grow + (j * 4 + r) * 32 + lane);
        cp_commit();
    }

    // ---- mask for this warp's 64 rows: 2 values/lane, served by shfl ----
    const int2 mreg = ((const int2*)(mask + (size_t)b * TT + w * 64))[lane];

    // ---- r from k0 ----
    if (tid < DD) s_r[tid] = g_r[(size_t)b * DD + tid];
    __syncthreads();

    const float srate = __fdividef(1.0f, 1.0f + __expf(-rate[0]));
    const float4 rr = ((const float4*)s_r)[lane];

    float4 acc0 = make_float4(0.f, 0.f, 0.f, 0.f);
    float4 acc1 = make_float4(0.f, 0.f, 0.f, 0.f);
    float  lacc = 0.0f;

    int sl_r = 0, sl_w = 2;                          // rotating ring slots
    #pragma unroll 4
    for (int i = 0; i < 16; i++) {                   // 16 iterations of 4 rows
        if (i + 2 < 16) {
            float4* slot = myring + sl_w * KA_STAGE_F4;
            #pragma unroll
            for (int r = 0; r < 4; r++)
                cp_async16(slot + r * 32 + lane, grow + ((i + 2) * 4 + r) * 32 + lane);
        }
        cp_commit();                      // commit every iter -> wait<2> = batch i done
        cp_wait<2>();

        const float4* slot = myring + sl_r * KA_STAGE_F4;
        const float4 c0 = slot[0 * 32 + lane];
        const float4 c1 = slot[1 * 32 + lane];
        const float4 c2 = slot[2 * 32 + lane];
        const float4 c3 = slot[3 * 32 + lane];

        float p0 = c0.x * rr.x + c0.y * rr.y + c0.z * rr.z + c0.w * rr.w;
        float p1 = c1.x * rr.x + c1.y * rr.y + c1.z * rr.z + c1.w * rr.w;
        float p2 = c2.x * rr.x + c2.y * rr.y + c2.z * rr.z + c2.w * rr.w;
        float p3 = c3.x * rr.x + c3.y * rr.y + c3.z * rr.z + c3.w * rr.w;

        // 9-shfl combined reduce: 8-lane group owns one row
        p0 += __shfl_xor_sync(0xffffffffu, p0, 16);
        p1 += __shfl_xor_sync(0xffffffffu, p1, 16);
        float v01 = (lane & 16) ? p1 : p0;
        p2 += __shfl_xor_sync(0xffffffffu, p2, 16);
        p3 += __shfl_xor_sync(0xffffffffu, p3, 16);
        float v23 = (lane & 16) ? p3 : p2;
        v01 += __shfl_xor_sync(0xffffffffu, v01, 8);
        v23 += __shfl_xor_sync(0xffffffffu, v23, 8);
        float v = (lane & 8) ? v23 : v01;
        v += __shfl_xor_sync(0xffffffffu, v, 4);
        v += __shfl_xor_sync(0xffffffffu, v, 2);
        v += __shfl_xor_sync(0xffffffffu, v, 1);

        // mask via shfl from registers (row 4i+myrow of this warp's 64)
        const int mloc = 4 * i + myrow;
        const int mx = __shfl_sync(0xffffffffu, mreg.x, mloc >> 1);
        const int my = __shfl_sync(0xffffffffu, mreg.y, mloc >> 1);
        const int m  = (mloc & 1) ? my : mx;

        // weight math once per 4 rows
        const int tg = w * 64 + mloc;                // global t (CTA covers full T)
        float sig   = __fdividef(1.0f, 1.0f + __expf(-v));
        float denom = srate * (__logf(2.72f + (1.0f - sig)) * (float)(TT - tg));
        float e     = fmaxf(__fdividef(sig, denom), 0.0f);
        float wgt   = (m != 0) ? __expf(e) : 0.0f;

        if ((lane & 7) == 0) {
            s_w[tg] = wgt;
            lacc += wgt;
        }
        float w0 = __shfl_sync(0xffffffffu, wgt, 0);
        float w1 = __shfl_sync(0xffffffffu, wgt, 16);
        float w2 = __shfl_sync(0xffffffffu, wgt, 8);
        float w3 = __shfl_sync(0xffffffffu, wgt, 24);

        acc0.x += w0 * c0.x + w1 * c1.x;
        acc0.y += w0 * c0.y + w1 * c1.y;
        acc0.z += w0 * c0.z + w1 * c1.z;
        acc0.w += w0 * c0.w + w1 * c1.w;
        acc1.x += w2 * c2.x + w3 * c3.x;
        acc1.y += w2 * c2.y + w3 * c3.y;
        acc1.z += w2 * c2.z + w3 * c3.z;
        acc1.w += w2 * c2.w + w3 * c3.w;

        sl_r = (sl_r == KA_STAGES - 1) ? 0 : sl_r + 1;
        sl_w = (sl_w == KA_STAGES - 1) ? 0 : sl_w + 1;
    }

    acc0.x += acc1.x; acc0.y += acc1.y; acc0.z += acc1.z; acc0.w += acc1.w;

    // ---- in-CTA finalize ----
    ((float4*)&s_v[w][0])[lane] = acc0;
    float lw = __shfl_sync(0xffffffffu, lacc, 0) + __shfl_sync(0xffffffffu, lacc, 8)
             + __shfl_sync(0xffffffffu, lacc, 16) + __shfl_sync(0xffffffffu, lacc, 24);
    if (lane == 0) s_l[w] = lw;
    __syncthreads();

    float l = s_l[0] + s_l[1] + s_l[2] + s_l[3]
            + s_l[4] + s_l[5] + s_l[6] + s_l[7];
    float inv = __fdividef(1.0f, l);

    if (out_a) {
        out_a[(size_t)b * TT + tid]       = s_w[tid] * inv;
        out_a[(size_t)b * TT + 256 + tid] = s_w[tid + 256] * inv;
    }
    if (out_v && tid < 32) {
        float4 v = make_float4(0.f, 0.f, 0.f, 0.f);
        #pragma unroll
        for (int g = 0; g < 8; g++) {
            float4 c = ((const float4*)&s_v[g][0])[tid];
            v.x += c.x; v.y += c.y; v.z += c.z; v.w += c.w;
        }
        v.x *= inv; v.y *= inv; v.z *= inv; v.w *= inv;
        ((float4*)(out_v + (size_t)b * DD))[tid] = v;
    }
}

// ================== launch ==================
extern "C" void kernel_launch(void* const* d_in, const int* in_sizes, int n_in,
                              void* d_out, int out_size) {
    const float* input = (const float*)d_in[0];
    const int*   mask  = (const int*)  d_in[1];
    const float* Wt    = (const float*)d_in[2];
    const float* Wx    = (const float*)d_in[3];
    const float* rate  = (const float*)d_in[4];

    float* out = (float*)d_out;
    float* out_v = nullptr;
    float* out_a = nullptr;

    if (out_size == BB * DD + BB * TT) {        // (v, a) concatenated
        out_v = out;
        out_a = out + BB * DD;
    } else if (out_size == BB * DD) {           // v only
        out_v = out;
    } else {                                    // a only
        out_a = out;
    }

    const int k0_smem = DD * HH * (int)sizeof(float);                     // 64 KB
    const int ka_smem = 8 * KA_STAGES * KA_STAGE_F4 * (int)sizeof(float4); // 48 KB
    static int smem_set = 0;
    if (!smem_set) {
        cudaFuncSetAttribute(k0_prologue,
                             cudaFuncAttributeMaxDynamicSharedMemorySize, k0_smem);
        cudaFuncSetAttribute(ka_single,
                             cudaFuncAttributeMaxDynamicSharedMemorySize, ka_smem);
        smem_set = 1;
    }

    k0_prologue<<<BB / 4, 256, k0_smem>>>(input, mask, Wt, Wx);
    ka_single  <<<BB, 256, ka_smem>>>(input, mask, rate, out_v, out_a);
}